// round 3
// baseline (speedup 1.0000x reference)
#include <cuda_runtime.h>
#include <cuda_bf16.h>
#include <cstdint>

#define N_HIT  50000
#define N_TRUE 512
#define N_EDGE 40000
#define DIM    8
#define MASK_WORDS (N_TRUE / 32)   // 16

// ---------------- scratch (no allocations allowed) ----------------
__device__ unsigned long long g_keys[N_TRUE];          // (f_bits<<32)|hit  packed argmax
__device__ unsigned int       g_mask[N_HIT * MASK_WORDS]; // membership bitmask
__device__ float              g_xc[N_TRUE * DIM];      // center coordinates
__device__ float              g_c2q[N_TRUE * 2];       // {|xc|^2, q_center}
__device__ float              g_b1sum;                 // sum f_centers
__device__ float              g_bkgsum;                // sum f over background
__device__ float              g_vsum;                  // sum_i q_i * sum_k v_ik*qc_k
__device__ int                g_nbkg;

// ---------------- kernel 1: zero everything ----------------
__global__ void k_init() {
    int idx = blockIdx.x * blockDim.x + threadIdx.x;
    if (idx < N_HIT * MASK_WORDS) g_mask[idx] = 0u;
    if (idx < N_TRUE) g_keys[idx] = 0ull;
    if (idx == 0) { g_b1sum = 0.f; g_bkgsum = 0.f; g_vsum = 0.f; g_nbkg = 0; }
}

// ---------------- kernel 2: edge scatter ----------------
// key = (float_bits(f[h]) << 32) | h.  f in (0.01,0.95) > 0 so the uint bit
// pattern is order-preserving; ties in f resolve to max hit id — exactly the
// reference's segment_max + "largest hit among max" semantics.
__global__ void k_edges(const float* __restrict__ f,
                        const int* __restrict__ e_h,
                        const int* __restrict__ e_p) {
    int e = blockIdx.x * blockDim.x + threadIdx.x;
    if (e >= N_EDGE) return;
    int h = e_h[e];
    int p = e_p[e];
    float fe = f[h];
    unsigned long long key =
        ((unsigned long long)__float_as_uint(fe) << 32) | (unsigned int)h;
    atomicMax(&g_keys[p], key);
    atomicOr(&g_mask[h * MASK_WORDS + (p >> 5)], 1u << (p & 31));
}

// ---------------- kernel 3: decode centers ----------------
__global__ void k_centers(const float* __restrict__ x) {
    int k = blockIdx.x * blockDim.x + threadIdx.x;
    if (k >= N_TRUE) return;
    unsigned long long key = g_keys[k];
    int c = (int)(unsigned int)(key & 0xffffffffu);
    float fc = __uint_as_float((unsigned int)(key >> 32));
    // f_centers clamp at 0 is a no-op: every particle has >=1 edge and f>0.
    float c2 = 0.f;
    #pragma unroll
    for (int d = 0; d < DIM; d++) {
        float v = x[c * DIM + d];
        g_xc[k * DIM + d] = v;
        c2 = fmaf(v, v, c2);
    }
    float a = atanhf(fc);
    g_c2q[2 * k + 0] = c2;
    g_c2q[2 * k + 1] = fmaf(a, a, 0.5f);  // q_center
    atomicAdd(&g_b1sum, fc);
}

// ---------------- kernel 4: main pairwise loss ----------------
__global__ __launch_bounds__(256)
void k_main(const float* __restrict__ x,
            const float* __restrict__ f,
            const int* __restrict__ y) {
    __shared__ float4 s_xc[N_TRUE * 2];   // 16 KB: 2 float4 per center
    __shared__ float2 s_cq[N_TRUE];       //  4 KB: {|xc|^2, qc}

    int tid = threadIdx.x;
    for (int t = tid; t < N_TRUE * 2; t += 256)
        s_xc[t] = ((const float4*)g_xc)[t];
    for (int t = tid; t < N_TRUE; t += 256)
        s_cq[t] = ((const float2*)g_c2q)[t];
    __syncthreads();

    int i = blockIdx.x * blockDim.x + tid;
    float contrib = 0.f;
    if (i < N_HIT) {
        const float4* x4 = (const float4*)x;
        float4 x0 = x4[i * 2 + 0];
        float4 x1 = x4[i * 2 + 1];
        float xi2 = x0.x*x0.x + x0.y*x0.y + x0.z*x0.z + x0.w*x0.w
                  + x1.x*x1.x + x1.y*x1.y + x1.z*x1.z + x1.w*x1.w;
        float fi = f[i];
        float a  = atanhf(fi);
        float qi = fmaf(a, a, 0.5f);

        if (y[i] == -1) {              // background term (rare: ~0.2% of hits)
            atomicAdd(&g_bkgsum, fi);
            atomicAdd(&g_nbkg, 1);
        }

        // membership bits for this hit: 16 words = 2x uint4
        const uint4* mw4 = (const uint4*)(g_mask + i * MASK_WORDS);
        uint4 ma = mw4[0], mb = mw4[1], mc = mw4[2], md = mw4[3];
        unsigned int mw[MASK_WORDS] = { ma.x, ma.y, ma.z, ma.w,
                                        mb.x, mb.y, mb.z, mb.w,
                                        mc.x, mc.y, mc.z, mc.w,
                                        md.x, md.y, md.z, md.w };
        float vsum = 0.f;
        #pragma unroll 1
        for (int w = 0; w < MASK_WORDS; w++) {
            unsigned int m = mw[w];
            #pragma unroll
            for (int b = 0; b < 32; b++) {
                int k = w * 32 + b;
                float4 c0 = s_xc[2 * k + 0];
                float4 c1 = s_xc[2 * k + 1];
                float2 cq = s_cq[k];
                // dist = xi2 + c2 - 2*dot  computed as -2*(dot - (xi2+c2)/2)
                float acc = -0.5f * (xi2 + cq.x);
                acc = fmaf(x0.x, c0.x, acc);
                acc = fmaf(x0.y, c0.y, acc);
                acc = fmaf(x0.z, c0.z, acc);
                acc = fmaf(x0.w, c0.w, acc);
                acc = fmaf(x1.x, c1.x, acc);
                acc = fmaf(x1.y, c1.y, acc);
                acc = fmaf(x1.z, c1.z, acc);
                acc = fmaf(x1.w, c1.w, acc);
                float dist = -2.f * acc;
                float v = ((m >> b) & 1u) ? dist : fmaxf(1.f - dist, 0.f);
                vsum = fmaf(v, cq.y, vsum);
            }
        }
        contrib = vsum * qi;
    }

    // warp reduce + one atomic per warp
    #pragma unroll
    for (int off = 16; off > 0; off >>= 1)
        contrib += __shfl_down_sync(0xffffffffu, contrib, off);
    if ((tid & 31) == 0)
        atomicAdd(&g_vsum, contrib);
}

// ---------------- kernel 5: finalize ----------------
__global__ void k_final(float* __restrict__ out) {
    float b1 = 1.f - g_b1sum / (float)N_TRUE;
    float b2 = g_bkgsum / (float)g_nbkg;   // S_B = 1
    out[0] = b1 + b2;
    out[1] = g_vsum / (float)N_HIT;
}

// ---------------- launch ----------------
extern "C" void kernel_launch(void* const* d_in, const int* in_sizes, int n_in,
                              void* d_out, int out_size) {
    const float* x   = (const float*)d_in[0];
    const float* f   = (const float*)d_in[1];
    const int*   y   = (const int*)d_in[2];
    const int*   e_h = (const int*)d_in[3];
    const int*   e_p = (const int*)d_in[4];
    float* out = (float*)d_out;

    k_init<<<(N_HIT * MASK_WORDS + 255) / 256, 256>>>();
    k_edges<<<(N_EDGE + 255) / 256, 256>>>(f, e_h, e_p);
    k_centers<<<(N_TRUE + 255) / 256, 256>>>(x);
    k_main<<<(N_HIT + 255) / 256, 256>>>(x, f, y);
    k_final<<<1, 1>>>(out);
}

// round 7
// speedup vs baseline: 1.3369x; 1.3369x over previous
#include <cuda_runtime.h>
#include <cuda_bf16.h>
#include <cstdint>

#define N_HIT  50000
#define N_TRUE 512
#define N_EDGE 40000
#define DIM    8
#define MASK_WORDS (N_TRUE / 32)   // 16
#define C_SPLIT 4                  // center quarters per hit tile
#define C_CHUNK (N_TRUE / C_SPLIT) // 128 centers per block
#define HIT_TILE 256

// ---------------- scratch (no allocations allowed) ----------------
__device__ unsigned long long g_keys[N_TRUE];             // (f_bits<<32)|hit packed argmax
__device__ unsigned int       g_mask[N_HIT * MASK_WORDS]; // membership bitmask
__device__ float              g_xc[N_TRUE * DIM];         // center coordinates
__device__ float              g_hq[N_TRUE * 2];           // {h = 0.5*(1-|xc|^2), qc2 = 2*q_center}
__device__ float              g_b1sum;
__device__ float              g_bkgsum;
__device__ float              g_vsum;
__device__ int                g_nbkg;

// ---------------- kernel 1: zero everything ----------------
__global__ void k_init() {
    int idx = blockIdx.x * blockDim.x + threadIdx.x;
    // zero mask with 16B stores
    if (idx < N_HIT * MASK_WORDS / 4)
        ((uint4*)g_mask)[idx] = make_uint4(0u, 0u, 0u, 0u);
    if (idx < N_TRUE) g_keys[idx] = 0ull;
    if (idx == 0) { g_b1sum = 0.f; g_bkgsum = 0.f; g_vsum = 0.f; g_nbkg = 0; }
}

// ---------------- kernel 2: edge scatter ----------------
// key = (float_bits(f[h]) << 32) | h.  f > 0 so the uint bit pattern is
// order-preserving; ties in f resolve to max hit id — exactly the reference's
// segment_max + "largest hit among edges attaining the max" semantics.
__global__ void k_edges(const float* __restrict__ f,
                        const int* __restrict__ e_h,
                        const int* __restrict__ e_p) {
    int e = blockIdx.x * blockDim.x + threadIdx.x;
    if (e >= N_EDGE) return;
    int h = e_h[e];
    int p = e_p[e];
    float fe = f[h];
    unsigned long long key =
        ((unsigned long long)__float_as_uint(fe) << 32) | (unsigned int)h;
    atomicMax(&g_keys[p], key);
    atomicOr(&g_mask[h * MASK_WORDS + (p >> 5)], 1u << (p & 31));
}

// ---------------- kernel 3: decode centers ----------------
__global__ void k_centers(const float* __restrict__ x) {
    int k = blockIdx.x * blockDim.x + threadIdx.x;
    if (k >= N_TRUE) return;
    unsigned long long key = g_keys[k];
    int c = (int)(unsigned int)(key & 0xffffffffu);
    float fc = __uint_as_float((unsigned int)(key >> 32));
    float c2 = 0.f;
    #pragma unroll
    for (int d = 0; d < DIM; d++) {
        float v = x[c * DIM + d];
        g_xc[k * DIM + d] = v;
        c2 = fmaf(v, v, c2);
    }
    float a  = atanhf(fc);
    float qc = fmaf(a, a, 0.5f);
    g_hq[2 * k + 0] = 0.5f * (1.f - c2);  // h
    g_hq[2 * k + 1] = 2.f * qc;           // qc2
    atomicAdd(&g_b1sum, fc);
}

// ---------------- kernel 4: main pairwise loss ----------------
// grid = (196 hit tiles, C_SPLIT center quarters). Each block: 256 hits x 128
// centers. Hinge term computed unconditionally (membership is ~0.8/512 sparse);
// member pairs corrected afterwards from the bitmask.
//   acc   = h_k - 0.5*|xi|^2 + xi.xc_k
//   dist  = 1 - 2*acc
//   hinge*qc = max(acc,0)*qc2
//   member correction: (dist - hinge)*qc = (0.5 - acc - max(acc,0))*qc2
__global__ __launch_bounds__(HIT_TILE)
void k_main(const float* __restrict__ x,
            const float* __restrict__ f,
            const int* __restrict__ y) {
    __shared__ float4 s_xc[C_CHUNK * 2];  // 4 KB
    __shared__ float2 s_hq[C_CHUNK];      // 1 KB
    __shared__ float  s_red[HIT_TILE / 32];

    int tid = threadIdx.x;
    int q   = blockIdx.y;                  // center quarter
    int k0  = q * C_CHUNK;

    for (int t = tid; t < C_CHUNK * 2; t += HIT_TILE)
        s_xc[t] = ((const float4*)g_xc)[k0 * 2 + t];
    for (int t = tid; t < C_CHUNK; t += HIT_TILE)
        s_hq[t] = ((const float2*)g_hq)[k0 + t];
    __syncthreads();

    int i = blockIdx.x * HIT_TILE + tid;
    float contrib = 0.f;
    if (i < N_HIT) {
        const float4* x4 = (const float4*)x;
        float4 x0 = x4[i * 2 + 0];
        float4 x1 = x4[i * 2 + 1];
        float xi2 = x0.x*x0.x + x0.y*x0.y + x0.z*x0.z + x0.w*x0.w
                  + x1.x*x1.x + x1.y*x1.y + x1.z*x1.z + x1.w*x1.w;
        float base = -0.5f * xi2;
        float fi = f[i];
        float a  = atanhf(fi);
        float qi = fmaf(a, a, 0.5f);

        if (q == 0 && y[i] == -1) {        // background term counted once
            atomicAdd(&g_bkgsum, fi);
            atomicAdd(&g_nbkg, 1);
        }

        float vsum = 0.f;
        #pragma unroll 4
        for (int k = 0; k < C_CHUNK; k++) {
            float4 c0 = s_xc[2 * k + 0];
            float4 c1 = s_xc[2 * k + 1];
            float2 hq = s_hq[k];
            float acc = hq.x + base;
            acc = fmaf(x0.x, c0.x, acc);
            acc = fmaf(x0.y, c0.y, acc);
            acc = fmaf(x0.z, c0.z, acc);
            acc = fmaf(x0.w, c0.w, acc);
            acc = fmaf(x1.x, c1.x, acc);
            acc = fmaf(x1.y, c1.y, acc);
            acc = fmaf(x1.z, c1.z, acc);
            acc = fmaf(x1.w, c1.w, acc);
            vsum = fmaf(fmaxf(acc, 0.f), hq.y, vsum);
        }

        // sparse member correction (avg ~0.2 bits per hit per quarter)
        uint4 mm = *(const uint4*)(g_mask + i * MASK_WORDS + q * 4);
        unsigned int mw[4] = { mm.x, mm.y, mm.z, mm.w };
        #pragma unroll
        for (int w = 0; w < 4; w++) {
            unsigned int m = mw[w];
            while (m) {
                int b = __ffs(m) - 1;
                m &= m - 1;
                int k = w * 32 + b;
                float4 c0 = s_xc[2 * k + 0];
                float4 c1 = s_xc[2 * k + 1];
                float2 hq = s_hq[k];
                float acc = hq.x + base;
                acc = fmaf(x0.x, c0.x, acc);
                acc = fmaf(x0.y, c0.y, acc);
                acc = fmaf(x0.z, c0.z, acc);
                acc = fmaf(x0.w, c0.w, acc);
                acc = fmaf(x1.x, c1.x, acc);
                acc = fmaf(x1.y, c1.y, acc);
                acc = fmaf(x1.z, c1.z, acc);
                acc = fmaf(x1.w, c1.w, acc);
                vsum += (0.5f - acc - fmaxf(acc, 0.f)) * hq.y;
            }
        }
        contrib = vsum * qi;
    }

    // block reduce -> single atomic
    #pragma unroll
    for (int off = 16; off > 0; off >>= 1)
        contrib += __shfl_down_sync(0xffffffffu, contrib, off);
    if ((tid & 31) == 0) s_red[tid >> 5] = contrib;
    __syncthreads();
    if (tid < 32) {
        float v = (tid < HIT_TILE / 32) ? s_red[tid] : 0.f;
        #pragma unroll
        for (int off = 4; off > 0; off >>= 1)
            v += __shfl_down_sync(0xffffffffu, v, off);
        if (tid == 0) atomicAdd(&g_vsum, v);
    }
}

// ---------------- kernel 5: finalize ----------------
__global__ void k_final(float* __restrict__ out) {
    float b1 = 1.f - g_b1sum / (float)N_TRUE;
    float b2 = g_bkgsum / (float)g_nbkg;   // S_B = 1
    out[0] = b1 + b2;
    out[1] = g_vsum / (float)N_HIT;
}

// ---------------- launch ----------------
extern "C" void kernel_launch(void* const* d_in, const int* in_sizes, int n_in,
                              void* d_out, int out_size) {
    const float* x   = (const float*)d_in[0];
    const float* f   = (const float*)d_in[1];
    const int*   y   = (const int*)d_in[2];
    const int*   e_h = (const int*)d_in[3];
    const int*   e_p = (const int*)d_in[4];
    float* out = (float*)d_out;

    k_init<<<(N_HIT * MASK_WORDS / 4 + 255) / 256, 256>>>();
    k_edges<<<(N_EDGE + 255) / 256, 256>>>(f, e_h, e_p);
    k_centers<<<(N_TRUE + 255) / 256, 256>>>(x);
    dim3 grid((N_HIT + HIT_TILE - 1) / HIT_TILE, C_SPLIT);
    k_main<<<grid, HIT_TILE>>>(x, f, y);
    k_final<<<1, 1>>>(out);
}

// round 8
// speedup vs baseline: 1.5246x; 1.1404x over previous
#include <cuda_runtime.h>
#include <cuda_bf16.h>
#include <cstdint>

#define N_HIT  50000
#define N_TRUE 512
#define N_EDGE 40000
#define DIM    8
#define MASK_WORDS (N_TRUE / 32)   // 16
#define C_SPLIT 4                  // center quarters
#define C_CHUNK (N_TRUE / C_SPLIT) // 128 centers per block
#define C_PAIRS (C_CHUNK / 2)      // 64 packed center pairs
#define TPB 256
#define HITS_PER_BLOCK (TPB * 2)   // 512 hits (2 per thread)

using u64 = unsigned long long;

// ---------------- packed f32x2 helpers (sm_103a FFMA2 path) ----------------
__device__ __forceinline__ u64 pack2(float lo, float hi) {
    u64 r; asm("mov.b64 %0, {%1, %2};" : "=l"(r) : "f"(lo), "f"(hi)); return r;
}
__device__ __forceinline__ void unpack2(u64 v, float& lo, float& hi) {
    asm("mov.b64 {%0, %1}, %2;" : "=f"(lo), "=f"(hi) : "l"(v));
}
__device__ __forceinline__ u64 fma2(u64 a, u64 b, u64 c) {
    u64 d; asm("fma.rn.f32x2 %0, %1, %2, %3;" : "=l"(d) : "l"(a), "l"(b), "l"(c)); return d;
}
__device__ __forceinline__ u64 add2(u64 a, u64 b) {
    u64 d; asm("add.rn.f32x2 %0, %1, %2;" : "=l"(d) : "l"(a), "l"(b)); return d;
}
__device__ __forceinline__ void lds_v2b64(unsigned addr, u64& a, u64& b) {
    asm volatile("ld.shared.v2.b64 {%0, %1}, [%2];" : "=l"(a), "=l"(b) : "r"(addr));
}

// ---------------- scratch (no allocations allowed) ----------------
__device__ u64          g_keys[N_TRUE];                // (f_bits<<32)|hit packed argmax
__device__ unsigned int g_mask[N_HIT * MASK_WORDS];    // membership bitmask
__device__ float        g_xc[N_TRUE * DIM];            // center coordinates
__device__ float        g_hq[N_TRUE * 2];              // {h = 0.5*(1-|xc|^2), qc2 = 2*q_center}
__device__ float        g_b1sum;
__device__ float        g_bkgsum;
__device__ float        g_vsum;
__device__ int          g_nbkg;

// ---------------- kernel 1: zero everything ----------------
__global__ void k_init() {
    int idx = blockIdx.x * blockDim.x + threadIdx.x;
    if (idx < N_HIT * MASK_WORDS / 4)
        ((uint4*)g_mask)[idx] = make_uint4(0u, 0u, 0u, 0u);
    if (idx < N_TRUE) g_keys[idx] = 0ull;
    if (idx == 0) { g_b1sum = 0.f; g_bkgsum = 0.f; g_vsum = 0.f; g_nbkg = 0; }
}

// ---------------- kernel 2: edge scatter ----------------
// key = (float_bits(f[h]) << 32) | h.  f > 0 so the uint bit pattern is
// order-preserving; ties in f resolve to max hit id — exactly the reference's
// segment_max + "largest hit among edges attaining the max" semantics.
__global__ void k_edges(const float* __restrict__ f,
                        const int* __restrict__ e_h,
                        const int* __restrict__ e_p) {
    int e = blockIdx.x * blockDim.x + threadIdx.x;
    if (e >= N_EDGE) return;
    int h = e_h[e];
    int p = e_p[e];
    float fe = f[h];
    u64 key = ((u64)__float_as_uint(fe) << 32) | (unsigned int)h;
    atomicMax(&g_keys[p], key);
    atomicOr(&g_mask[h * MASK_WORDS + (p >> 5)], 1u << (p & 31));
}

// ---------------- kernel 3: decode centers ----------------
__global__ void k_centers(const float* __restrict__ x) {
    int k = blockIdx.x * blockDim.x + threadIdx.x;
    if (k >= N_TRUE) return;
    u64 key = g_keys[k];
    int c = (int)(unsigned int)(key & 0xffffffffu);
    float fc = __uint_as_float((unsigned int)(key >> 32));
    float c2 = 0.f;
    #pragma unroll
    for (int d = 0; d < DIM; d++) {
        float v = x[c * DIM + d];
        g_xc[k * DIM + d] = v;
        c2 = fmaf(v, v, c2);
    }
    float a  = atanhf(fc);
    float qc = fmaf(a, a, 0.5f);
    g_hq[2 * k + 0] = 0.5f * (1.f - c2);  // h
    g_hq[2 * k + 1] = 2.f * qc;           // qc2
    atomicAdd(&g_b1sum, fc);
}

// ---------------- kernel 4: main pairwise loss ----------------
// Each block: 512 hits (2/thread) x 128 centers (64 packed pairs).
//   acc_k = h_k - 0.5*|xi|^2 + xi.xc_k      (FFMA2: two centers per op)
//   hinge*qc = max(acc,0)*qc2
//   member correction: + (0.5 - acc - max(acc,0))*qc2   (sparse, ~0.8 bits/hit)
__global__ __launch_bounds__(TPB)
void k_main(const float* __restrict__ x,
            const float* __restrict__ f,
            const int* __restrict__ y) {
    // pair p occupies 16 floats: [d0k0,d0k1,d1k0,d1k1, ..., d7k0,d7k1]
    __shared__ float  s_cf[C_PAIRS * 16];   // 4 KB
    __shared__ float4 s_hq4[C_PAIRS];       // 1 KB: {h0,h1,q0,q1}
    __shared__ float  s_red[TPB / 32];

    int tid = threadIdx.x;
    int q   = blockIdx.y;
    int k0  = q * C_CHUNK;

    // build packed center tiles
    {
        int p = tid >> 2, j = tid & 3;          // tid < 256 = 64 pairs * 4 dim-pairs
        const float* c0 = g_xc + (k0 + 2 * p) * DIM;
        const float* c1 = c0 + DIM;
        float* dst = s_cf + p * 16 + j * 4;
        dst[0] = c0[2 * j];     dst[1] = c1[2 * j];
        dst[2] = c0[2 * j + 1]; dst[3] = c1[2 * j + 1];
        if (tid < C_PAIRS) {
            const float* hq = g_hq + (k0 + 2 * tid) * 2;
            s_hq4[tid] = make_float4(hq[0], hq[2], hq[1], hq[3]); // {h0,h1,q0,q1}
        }
    }
    __syncthreads();

    unsigned s_c_base = (unsigned)__cvta_generic_to_shared(s_cf);

    int i0 = blockIdx.x * HITS_PER_BLOCK + tid;
    int i1 = i0 + TPB;
    bool v1 = (i1 < N_HIT);   // i0 always valid for this grid

    // per-hit setup: broadcast-packed coordinates
    const float4* x4 = (const float4*)x;
    float4 a0 = x4[i0 * 2], a1 = x4[i0 * 2 + 1];
    float4 b0_, b1_;
    if (v1) { b0_ = x4[i1 * 2]; b1_ = x4[i1 * 2 + 1]; }
    else    { b0_ = make_float4(0,0,0,0); b1_ = b0_; }

    u64 xa[8] = { pack2(a0.x,a0.x), pack2(a0.y,a0.y), pack2(a0.z,a0.z), pack2(a0.w,a0.w),
                  pack2(a1.x,a1.x), pack2(a1.y,a1.y), pack2(a1.z,a1.z), pack2(a1.w,a1.w) };
    u64 xb[8] = { pack2(b0_.x,b0_.x), pack2(b0_.y,b0_.y), pack2(b0_.z,b0_.z), pack2(b0_.w,b0_.w),
                  pack2(b1_.x,b1_.x), pack2(b1_.y,b1_.y), pack2(b1_.z,b1_.z), pack2(b1_.w,b1_.w) };

    float xi2a = a0.x*a0.x + a0.y*a0.y + a0.z*a0.z + a0.w*a0.w
               + a1.x*a1.x + a1.y*a1.y + a1.z*a1.z + a1.w*a1.w;
    float xi2b = b0_.x*b0_.x + b0_.y*b0_.y + b0_.z*b0_.z + b0_.w*b0_.w
               + b1_.x*b1_.x + b1_.y*b1_.y + b1_.z*b1_.z + b1_.w*b1_.w;
    float basea = -0.5f * xi2a, baseb = -0.5f * xi2b;
    u64 base2a = pack2(basea, basea), base2b = pack2(baseb, baseb);

    float fa = f[i0];
    float fb = v1 ? f[i1] : 0.5f;
    float ta = atanhf(fa), tb = atanhf(fb);
    float qa = fmaf(ta, ta, 0.5f), qb = fmaf(tb, tb, 0.5f);

    if (q == 0) {
        if (y[i0] == -1) { atomicAdd(&g_bkgsum, fa); atomicAdd(&g_nbkg, 1); }
        if (v1 && y[i1] == -1) { atomicAdd(&g_bkgsum, fb); atomicAdd(&g_nbkg, 1); }
    }

    float vsa = 0.f, vsb = 0.f;
    #pragma unroll 4
    for (int p = 0; p < C_PAIRS; p++) {
        unsigned addr = s_c_base + p * 64;
        u64 d0, d1, d2, d3, d4, d5, d6, d7;
        lds_v2b64(addr,      d0, d1);
        lds_v2b64(addr + 16, d2, d3);
        lds_v2b64(addr + 32, d4, d5);
        lds_v2b64(addr + 48, d6, d7);
        float4 hq = s_hq4[p];
        u64 hpair = pack2(hq.x, hq.y);

        u64 acc = add2(hpair, base2a);
        acc = fma2(xa[0], d0, acc); acc = fma2(xa[1], d1, acc);
        acc = fma2(xa[2], d2, acc); acc = fma2(xa[3], d3, acc);
        acc = fma2(xa[4], d4, acc); acc = fma2(xa[5], d5, acc);
        acc = fma2(xa[6], d6, acc); acc = fma2(xa[7], d7, acc);
        float lo, hi; unpack2(acc, lo, hi);
        vsa = fmaf(fmaxf(lo, 0.f), hq.z, vsa);
        vsa = fmaf(fmaxf(hi, 0.f), hq.w, vsa);

        u64 acc2 = add2(hpair, base2b);
        acc2 = fma2(xb[0], d0, acc2); acc2 = fma2(xb[1], d1, acc2);
        acc2 = fma2(xb[2], d2, acc2); acc2 = fma2(xb[3], d3, acc2);
        acc2 = fma2(xb[4], d4, acc2); acc2 = fma2(xb[5], d5, acc2);
        acc2 = fma2(xb[6], d6, acc2); acc2 = fma2(xb[7], d7, acc2);
        float lo2, hi2; unpack2(acc2, lo2, hi2);
        vsb = fmaf(fmaxf(lo2, 0.f), hq.z, vsb);
        vsb = fmaf(fmaxf(hi2, 0.f), hq.w, vsb);
    }

    // sparse member correction: scalar recompute from packed smem layout
    // c[k][d] = s_cf[(k>>1)*16 + d*2 + (k&1)]
    {
        uint4 mm = *(const uint4*)(g_mask + i0 * MASK_WORDS + q * 4);
        unsigned int mw0[4] = { mm.x, mm.y, mm.z, mm.w };
        uint4 nn = v1 ? *(const uint4*)(g_mask + i1 * MASK_WORDS + q * 4)
                      : make_uint4(0u, 0u, 0u, 0u);
        unsigned int mw1[4] = { nn.x, nn.y, nn.z, nn.w };

        #pragma unroll
        for (int hsel = 0; hsel < 2; hsel++) {
            const float4* X0 = hsel ? &b0_ : &a0;
            const float4* X1 = hsel ? &b1_ : &a1;
            float base = hsel ? baseb : basea;
            unsigned int* mw = hsel ? mw1 : mw0;
            float corr = 0.f;
            #pragma unroll
            for (int w = 0; w < 4; w++) {
                unsigned int m = mw[w];
                while (m) {
                    int b = __ffs(m) - 1;
                    m &= m - 1;
                    int k = w * 32 + b;
                    const float* cf = s_cf + (k >> 1) * 16 + (k & 1);
                    float4 hq = s_hq4[k >> 1];
                    float h  = (k & 1) ? hq.y : hq.x;
                    float qc = (k & 1) ? hq.w : hq.z;
                    float acc = h + base;
                    acc = fmaf(X0->x, cf[0],  acc);
                    acc = fmaf(X0->y, cf[2],  acc);
                    acc = fmaf(X0->z, cf[4],  acc);
                    acc = fmaf(X0->w, cf[6],  acc);
                    acc = fmaf(X1->x, cf[8],  acc);
                    acc = fmaf(X1->y, cf[10], acc);
                    acc = fmaf(X1->z, cf[12], acc);
                    acc = fmaf(X1->w, cf[14], acc);
                    corr += (0.5f - acc - fmaxf(acc, 0.f)) * qc;
                }
            }
            if (hsel) vsb += corr; else vsa += corr;
        }
    }

    float contrib = vsa * qa + (v1 ? vsb * qb : 0.f);

    // block reduce -> single atomic
    #pragma unroll
    for (int off = 16; off > 0; off >>= 1)
        contrib += __shfl_down_sync(0xffffffffu, contrib, off);
    if ((tid & 31) == 0) s_red[tid >> 5] = contrib;
    __syncthreads();
    if (tid < 32) {
        float v = (tid < TPB / 32) ? s_red[tid] : 0.f;
        #pragma unroll
        for (int off = 4; off > 0; off >>= 1)
            v += __shfl_down_sync(0xffffffffu, v, off);
        if (tid == 0) atomicAdd(&g_vsum, v);
    }
}

// ---------------- kernel 5: finalize ----------------
__global__ void k_final(float* __restrict__ out) {
    float b1 = 1.f - g_b1sum / (float)N_TRUE;
    float b2 = g_bkgsum / (float)g_nbkg;   // S_B = 1
    out[0] = b1 + b2;
    out[1] = g_vsum / (float)N_HIT;
}

// ---------------- launch ----------------
extern "C" void kernel_launch(void* const* d_in, const int* in_sizes, int n_in,
                              void* d_out, int out_size) {
    const float* x   = (const float*)d_in[0];
    const float* f   = (const float*)d_in[1];
    const int*   y   = (const int*)d_in[2];
    const int*   e_h = (const int*)d_in[3];
    const int*   e_p = (const int*)d_in[4];
    float* out = (float*)d_out;

    k_init<<<(N_HIT * MASK_WORDS / 4 + 255) / 256, 256>>>();
    k_edges<<<(N_EDGE + 255) / 256, 256>>>(f, e_h, e_p);
    k_centers<<<(N_TRUE + 255) / 256, 256>>>(x);
    dim3 grid((N_HIT + HITS_PER_BLOCK - 1) / HITS_PER_BLOCK, C_SPLIT);
    k_main<<<grid, TPB>>>(x, f, y);
    k_final<<<1, 1>>>(out);
}

// round 10
// speedup vs baseline: 1.6515x; 1.0832x over previous
#include <cuda_runtime.h>
#include <cuda_bf16.h>
#include <cstdint>

#define N_HIT  50000
#define N_TRUE 512
#define N_EDGE 40000
#define DIM    8
#define MASK_WORDS (N_TRUE / 32)   // 16
#define C_SPLIT 8                  // center eighths
#define C_CHUNK (N_TRUE / C_SPLIT) // 64 centers per block
#define C_PAIRS (C_CHUNK / 2)      // 32 packed center pairs
#define TPB 256
#define HITS_PER_BLOCK (TPB * 2)   // 512 hits (2 per thread)
#define GRID_X ((N_HIT + HITS_PER_BLOCK - 1) / HITS_PER_BLOCK)  // 98

using u64 = unsigned long long;

// ---------------- packed f32x2 helpers (sm_103a FFMA2 path) ----------------
__device__ __forceinline__ u64 pack2(float lo, float hi) {
    u64 r; asm("mov.b64 %0, {%1, %2};" : "=l"(r) : "f"(lo), "f"(hi)); return r;
}
__device__ __forceinline__ void unpack2(u64 v, float& lo, float& hi) {
    asm("mov.b64 {%0, %1}, %2;" : "=f"(lo), "=f"(hi) : "l"(v));
}
__device__ __forceinline__ u64 fma2(u64 a, u64 b, u64 c) {
    u64 d; asm("fma.rn.f32x2 %0, %1, %2, %3;" : "=l"(d) : "l"(a), "l"(b), "l"(c)); return d;
}
__device__ __forceinline__ u64 add2(u64 a, u64 b) {
    u64 d; asm("add.rn.f32x2 %0, %1, %2;" : "=l"(d) : "l"(a), "l"(b)); return d;
}
__device__ __forceinline__ void lds_v2b64(unsigned addr, u64& a, u64& b) {
    asm volatile("ld.shared.v2.b64 {%0, %1}, [%2];" : "=l"(a), "=l"(b) : "r"(addr));
}

// ---------------- scratch (no allocations allowed) ----------------
__device__ u64          g_keys[N_TRUE];                // (f_bits<<32)|hit packed argmax
__device__ unsigned int g_mask[N_HIT * MASK_WORDS];    // membership bitmask
__device__ float        g_xc[N_TRUE * DIM];            // center coordinates
__device__ float        g_hq[N_TRUE * 2];              // {h = 0.5*(1-|xc|^2), qc2 = 2*q_center}
__device__ float        g_b1sum;
__device__ float        g_bkgsum;
__device__ float        g_vsum;
__device__ int          g_nbkg;
__device__ int          g_done;                        // zero-init; reset by last block

// ---------------- kernel 1: zero everything ----------------
__global__ void k_init() {
    int idx = blockIdx.x * blockDim.x + threadIdx.x;
    if (idx < N_HIT * MASK_WORDS / 4)
        ((uint4*)g_mask)[idx] = make_uint4(0u, 0u, 0u, 0u);
    if (idx < N_TRUE) g_keys[idx] = 0ull;
    if (idx == 0) { g_b1sum = 0.f; g_bkgsum = 0.f; g_vsum = 0.f; g_nbkg = 0; g_done = 0; }
}

// ---------------- kernel 2: edge scatter ----------------
// key = (float_bits(f[h]) << 32) | h.  f > 0 so the uint bit pattern is
// order-preserving; ties in f resolve to max hit id — exactly the reference's
// segment_max + "largest hit among edges attaining the max" semantics.
__global__ void k_edges(const float* __restrict__ f,
                        const int* __restrict__ e_h,
                        const int* __restrict__ e_p) {
    int e = blockIdx.x * blockDim.x + threadIdx.x;
    if (e >= N_EDGE) return;
    int h = e_h[e];
    int p = e_p[e];
    float fe = f[h];
    u64 key = ((u64)__float_as_uint(fe) << 32) | (unsigned int)h;
    atomicMax(&g_keys[p], key);
    atomicOr(&g_mask[h * MASK_WORDS + (p >> 5)], 1u << (p & 31));
}

// ---------------- kernel 3: decode centers ----------------
__global__ void k_centers(const float* __restrict__ x) {
    int k = blockIdx.x * blockDim.x + threadIdx.x;
    if (k >= N_TRUE) return;
    u64 key = g_keys[k];
    int c = (int)(unsigned int)(key & 0xffffffffu);
    float fc = __uint_as_float((unsigned int)(key >> 32));
    float c2 = 0.f;
    #pragma unroll
    for (int d = 0; d < DIM; d++) {
        float v = x[c * DIM + d];
        g_xc[k * DIM + d] = v;
        c2 = fmaf(v, v, c2);
    }
    float a  = atanhf(fc);
    float qc = fmaf(a, a, 0.5f);
    g_hq[2 * k + 0] = 0.5f * (1.f - c2);  // h
    g_hq[2 * k + 1] = 2.f * qc;           // qc2
    atomicAdd(&g_b1sum, fc);
}

// ---------------- kernel 4: main pairwise loss (+ fused finalize) ----------------
// Each block: 512 hits (2/thread) x 64 centers (32 packed pairs).
//   acc_k = h_k - 0.5*|xi|^2 + xi.xc_k      (FFMA2: two centers per op)
//   hinge*qc = max(acc,0)*qc2
//   member correction: + (0.5 - acc - max(acc,0))*qc2   (sparse, ~0.8 bits/hit)
__global__ __launch_bounds__(TPB)
void k_main(const float* __restrict__ x,
            const float* __restrict__ f,
            const int* __restrict__ y,
            float* __restrict__ out) {
    // pair p occupies 16 floats: [d0k0,d0k1,d1k0,d1k1, ..., d7k0,d7k1]
    __shared__ float  s_cf[C_PAIRS * 16];   // 2 KB
    __shared__ float4 s_hq4[C_PAIRS];       // 512 B: {h0,h1,q0,q1}
    __shared__ float  s_red[TPB / 32];

    int tid = threadIdx.x;
    int q   = blockIdx.y;
    int k0  = q * C_CHUNK;

    // build packed center tiles (128 threads for coords, 32 for hq)
    if (tid < C_PAIRS * 4) {
        int p = tid >> 2, j = tid & 3;
        const float* c0 = g_xc + (k0 + 2 * p) * DIM;
        const float* c1 = c0 + DIM;
        float* dst = s_cf + p * 16 + j * 4;
        dst[0] = c0[2 * j];     dst[1] = c1[2 * j];
        dst[2] = c0[2 * j + 1]; dst[3] = c1[2 * j + 1];
    }
    if (tid < C_PAIRS) {
        const float* hq = g_hq + (k0 + 2 * tid) * 2;
        s_hq4[tid] = make_float4(hq[0], hq[2], hq[1], hq[3]); // {h0,h1,q0,q1}
    }
    __syncthreads();

    unsigned s_c_base = (unsigned)__cvta_generic_to_shared(s_cf);

    int i0 = blockIdx.x * HITS_PER_BLOCK + tid;
    int i1 = i0 + TPB;
    bool v1 = (i1 < N_HIT);   // i0 always valid for this grid

    // per-hit setup: broadcast-packed coordinates
    const float4* x4 = (const float4*)x;
    float4 a0 = x4[i0 * 2], a1 = x4[i0 * 2 + 1];
    float4 b0_, b1_;
    if (v1) { b0_ = x4[i1 * 2]; b1_ = x4[i1 * 2 + 1]; }
    else    { b0_ = make_float4(0,0,0,0); b1_ = b0_; }

    u64 xa[8] = { pack2(a0.x,a0.x), pack2(a0.y,a0.y), pack2(a0.z,a0.z), pack2(a0.w,a0.w),
                  pack2(a1.x,a1.x), pack2(a1.y,a1.y), pack2(a1.z,a1.z), pack2(a1.w,a1.w) };
    u64 xb[8] = { pack2(b0_.x,b0_.x), pack2(b0_.y,b0_.y), pack2(b0_.z,b0_.z), pack2(b0_.w,b0_.w),
                  pack2(b1_.x,b1_.x), pack2(b1_.y,b1_.y), pack2(b1_.z,b1_.z), pack2(b1_.w,b1_.w) };

    float xi2a = a0.x*a0.x + a0.y*a0.y + a0.z*a0.z + a0.w*a0.w
               + a1.x*a1.x + a1.y*a1.y + a1.z*a1.z + a1.w*a1.w;
    float xi2b = b0_.x*b0_.x + b0_.y*b0_.y + b0_.z*b0_.z + b0_.w*b0_.w
               + b1_.x*b1_.x + b1_.y*b1_.y + b1_.z*b1_.z + b1_.w*b1_.w;
    float basea = -0.5f * xi2a, baseb = -0.5f * xi2b;
    u64 base2a = pack2(basea, basea), base2b = pack2(baseb, baseb);

    float fa = f[i0];
    float fb = v1 ? f[i1] : 0.5f;
    float ta = atanhf(fa), tb = atanhf(fb);
    float qa = fmaf(ta, ta, 0.5f), qb = fmaf(tb, tb, 0.5f);

    if (q == 0) {
        if (y[i0] == -1) { atomicAdd(&g_bkgsum, fa); atomicAdd(&g_nbkg, 1); }
        if (v1 && y[i1] == -1) { atomicAdd(&g_bkgsum, fb); atomicAdd(&g_nbkg, 1); }
    }

    float vsa = 0.f, vsb = 0.f;
    #pragma unroll 4
    for (int p = 0; p < C_PAIRS; p++) {
        unsigned addr = s_c_base + p * 64;
        u64 d0, d1, d2, d3, d4, d5, d6, d7;
        lds_v2b64(addr,      d0, d1);
        lds_v2b64(addr + 16, d2, d3);
        lds_v2b64(addr + 32, d4, d5);
        lds_v2b64(addr + 48, d6, d7);
        float4 hq = s_hq4[p];
        u64 hpair = pack2(hq.x, hq.y);

        u64 acc = add2(hpair, base2a);
        acc = fma2(xa[0], d0, acc); acc = fma2(xa[1], d1, acc);
        acc = fma2(xa[2], d2, acc); acc = fma2(xa[3], d3, acc);
        acc = fma2(xa[4], d4, acc); acc = fma2(xa[5], d5, acc);
        acc = fma2(xa[6], d6, acc); acc = fma2(xa[7], d7, acc);
        float lo, hi; unpack2(acc, lo, hi);
        vsa = fmaf(fmaxf(lo, 0.f), hq.z, vsa);
        vsa = fmaf(fmaxf(hi, 0.f), hq.w, vsa);

        u64 acc2 = add2(hpair, base2b);
        acc2 = fma2(xb[0], d0, acc2); acc2 = fma2(xb[1], d1, acc2);
        acc2 = fma2(xb[2], d2, acc2); acc2 = fma2(xb[3], d3, acc2);
        acc2 = fma2(xb[4], d4, acc2); acc2 = fma2(xb[5], d5, acc2);
        acc2 = fma2(xb[6], d6, acc2); acc2 = fma2(xb[7], d7, acc2);
        float lo2, hi2; unpack2(acc2, lo2, hi2);
        vsb = fmaf(fmaxf(lo2, 0.f), hq.z, vsb);
        vsb = fmaf(fmaxf(hi2, 0.f), hq.w, vsb);
    }

    // sparse member correction: scalar recompute from packed smem layout
    // c[k][d] = s_cf[(k>>1)*16 + d*2 + (k&1)]
    {
        uint2 mm = *(const uint2*)(g_mask + i0 * MASK_WORDS + q * 2);
        unsigned int mw0[2] = { mm.x, mm.y };
        uint2 nn = v1 ? *(const uint2*)(g_mask + i1 * MASK_WORDS + q * 2)
                      : make_uint2(0u, 0u);
        unsigned int mw1[2] = { nn.x, nn.y };

        #pragma unroll
        for (int hsel = 0; hsel < 2; hsel++) {
            const float4* X0 = hsel ? &b0_ : &a0;
            const float4* X1 = hsel ? &b1_ : &a1;
            float base = hsel ? baseb : basea;
            unsigned int* mw = hsel ? mw1 : mw0;
            float corr = 0.f;
            #pragma unroll
            for (int w = 0; w < 2; w++) {
                unsigned int m = mw[w];
                while (m) {
                    int b = __ffs(m) - 1;
                    m &= m - 1;
                    int k = w * 32 + b;
                    const float* cf = s_cf + (k >> 1) * 16 + (k & 1);
                    float4 hq = s_hq4[k >> 1];
                    float h  = (k & 1) ? hq.y : hq.x;
                    float qc = (k & 1) ? hq.w : hq.z;
                    float acc = h + base;
                    acc = fmaf(X0->x, cf[0],  acc);
                    acc = fmaf(X0->y, cf[2],  acc);
                    acc = fmaf(X0->z, cf[4],  acc);
                    acc = fmaf(X0->w, cf[6],  acc);
                    acc = fmaf(X1->x, cf[8],  acc);
                    acc = fmaf(X1->y, cf[10], acc);
                    acc = fmaf(X1->z, cf[12], acc);
                    acc = fmaf(X1->w, cf[14], acc);
                    corr += (0.5f - acc - fmaxf(acc, 0.f)) * qc;
                }
            }
            if (hsel) vsb += corr; else vsa += corr;
        }
    }

    float contrib = vsa * qa + (v1 ? vsb * qb : 0.f);

    // block reduce -> single atomic
    #pragma unroll
    for (int off = 16; off > 0; off >>= 1)
        contrib += __shfl_down_sync(0xffffffffu, contrib, off);
    if ((tid & 31) == 0) s_red[tid >> 5] = contrib;
    __syncthreads();
    if (tid < 32) {
        float v = (tid < TPB / 32) ? s_red[tid] : 0.f;
        #pragma unroll
        for (int off = 4; off > 0; off >>= 1)
            v += __shfl_down_sync(0xffffffffu, v, off);
        if (tid == 0) atomicAdd(&g_vsum, v);
    }

    // fused finalize: last block to finish computes the outputs
    if (tid == 0) {
        __threadfence();
        int done = atomicAdd(&g_done, 1);
        if (done == GRID_X * C_SPLIT - 1) {
            float vsum   = atomicAdd(&g_vsum, 0.f);
            float bkgsum = atomicAdd(&g_bkgsum, 0.f);
            int   nbkg   = atomicAdd(&g_nbkg, 0);
            float b1sum  = atomicAdd(&g_b1sum, 0.f);
            float b1 = 1.f - b1sum / (float)N_TRUE;
            float b2 = bkgsum / (float)nbkg;   // S_B = 1
            out[0] = b1 + b2;
            out[1] = vsum / (float)N_HIT;
            g_done = 0;                        // reset for next call
        }
    }
}

// ---------------- launch ----------------
extern "C" void kernel_launch(void* const* d_in, const int* in_sizes, int n_in,
                              void* d_out, int out_size) {
    const float* x   = (const float*)d_in[0];
    const float* f   = (const float*)d_in[1];
    const int*   y   = (const int*)d_in[2];
    const int*   e_h = (const int*)d_in[3];
    const int*   e_p = (const int*)d_in[4];
    float* out = (float*)d_out;

    k_init<<<(N_HIT * MASK_WORDS / 4 + 255) / 256, 256>>>();
    k_edges<<<(N_EDGE + 255) / 256, 256>>>(f, e_h, e_p);
    k_centers<<<(N_TRUE + 255) / 256, 256>>>(x);
    dim3 grid(GRID_X, C_SPLIT);
    k_main<<<grid, TPB>>>(x, f, y, out);
}